// round 16
// baseline (speedup 1.0000x reference)
#include <cuda_runtime.h>
#include <cuda_bf16.h>
#include <cuda_fp16.h>
#include <math.h>
#include <stdint.h>

// Problem constants
#define E_    16
#define H_    1024
#define D_    2048
#define R_    16
#define T_    1024
#define NSLOT 2048
#define NPAD  (NSLOT + 128)
#define LIMIT_   7.0f
#define ACT_ALPHA_ 1.702f

// ---------------- device scratch (~9.1 MB total) ----------------------------
__device__ int    d_count[E_];
__device__ int    d_off[E_];
__device__ int    d_slot_token[NSLOT];
__device__ int    d_slot_expert[NSLOT];
__device__ float  d_slot_w[NSLOT];
__device__ __half d_xh[(size_t)NPAD * 1024];   // gathered x, f16
__device__ __half d_gh[(size_t)NPAD * 1024];   // glu out, f16
__device__ __half d_r1[(size_t)NPAD * R_];     // lora acts f16
__device__ __half d_r2[(size_t)NPAD * R_];

// ---------------- helpers ----------------------------------------------------
__device__ __forceinline__ uint32_t smem_u32(const void* p) {
    return (uint32_t)__cvta_generic_to_shared(p);
}
__device__ __forceinline__ uint2 cvt4h(const float4 a) {
    uint2 r;
    asm("cvt.rn.f16x2.f32 %0, %1, %2;" : "=r"(r.x) : "f"(a.y), "f"(a.x));
    asm("cvt.rn.f16x2.f32 %0, %1, %2;" : "=r"(r.y) : "f"(a.w), "f"(a.z));
    return r;
}
__device__ __forceinline__ uint4 cvt8_f16(const float4 a, const float4 b) {
    uint4 r;
    asm("cvt.rn.f16x2.f32 %0, %1, %2;" : "=r"(r.x) : "f"(a.y), "f"(a.x));
    asm("cvt.rn.f16x2.f32 %0, %1, %2;" : "=r"(r.y) : "f"(a.w), "f"(a.z));
    asm("cvt.rn.f16x2.f32 %0, %1, %2;" : "=r"(r.z) : "f"(b.y), "f"(b.x));
    asm("cvt.rn.f16x2.f32 %0, %1, %2;" : "=r"(r.w) : "f"(b.w), "f"(b.z));
    return r;
}
__device__ __forceinline__ void ldsm4(uint32_t* r, uint32_t addr) {
    asm volatile("ldmatrix.sync.aligned.m8n8.x4.shared.b16 {%0,%1,%2,%3}, [%4];"
                 : "=r"(r[0]), "=r"(r[1]), "=r"(r[2]), "=r"(r[3]) : "r"(addr));
}
__device__ __forceinline__ void ldsm4t(uint32_t* r, uint32_t addr) {
    asm volatile("ldmatrix.sync.aligned.m8n8.x4.trans.shared.b16 {%0,%1,%2,%3}, [%4];"
                 : "=r"(r[0]), "=r"(r[1]), "=r"(r[2]), "=r"(r[3]) : "r"(addr));
}
__device__ __forceinline__ void mma16816f(float* d, const uint32_t* a,
                                          const uint32_t* b) {
    asm volatile(
        "mma.sync.aligned.m16n8k16.row.col.f32.f16.f16.f32 "
        "{%0,%1,%2,%3}, {%4,%5,%6,%7}, {%8,%9}, {%0,%1,%2,%3};"
        : "+f"(d[0]), "+f"(d[1]), "+f"(d[2]), "+f"(d[3])
        : "r"(a[0]), "r"(a[1]), "r"(a[2]), "r"(a[3]), "r"(b[0]), "r"(b[1]));
}

// ---------------- routing ---------------------------------------------------
__global__ void route_kernel(const int* __restrict__ ridx,
                             const float* __restrict__ rw) {
    __shared__ int cnt[E_], cur[E_], soff[E_ + 1];
    int t = threadIdx.x;
    if (t < E_) { cnt[t] = 0; cur[t] = 0; }
    __syncthreads();
    for (int i = t; i < NSLOT; i += blockDim.x)
        atomicAdd(&cnt[ridx[i]], 1);
    __syncthreads();
    if (t == 0) {
        int s = 0;
        for (int e = 0; e < E_; e++) { soff[e] = s; s += cnt[e]; }
        soff[E_] = s;
    }
    __syncthreads();
    for (int i = t; i < NSLOT; i += blockDim.x) {
        int e = ridx[i];
        int slot = soff[e] + atomicAdd(&cur[e], 1);
        d_slot_token[slot]  = i >> 1;
        d_slot_expert[slot] = e;
        d_slot_w[slot]      = rw[i];
    }
    if (t < E_) { d_count[t] = cnt[t]; d_off[t] = soff[t]; }
}

// ---------------- zero output ------------------------------------------------
__global__ void zero_out_kernel(float* __restrict__ out) {
    int i = blockIdx.x * 256 + threadIdx.x;
    *(float4*)&out[(size_t)i * 4] = make_float4(0.f, 0.f, 0.f, 0.f);
}

// ---------------- gather x rows -> f16 slot rows -----------------------------
__global__ void gather_xh_kernel(const float* __restrict__ x) {
    int slot = blockIdx.x;
    int tok  = d_slot_token[slot];
    int c    = threadIdx.x * 4;
    float4 v = __ldg((const float4*)&x[(size_t)tok * 1024 + c]);
    *(uint2*)&d_xh[(size_t)slot * 1024 + c] = cvt4h(v);
}

// ---------------- LoRA rank projection: 32 slots/block, A staged in SMEM ----
// r[slot][0..15] = act_row(slot) . A_e     (f16 acts in, f16 r out)
template <bool STAGE1>
__global__ __launch_bounds__(256)
void lora_r_kernel(const float* __restrict__ A) {  // [E,1024,16] fp32
    const int e   = blockIdx.y;
    const int ne  = d_count[e];
    const int off = d_off[e];
    const float* Ae = A + (size_t)e * 1024 * R_;
    const __half* Xs = STAGE1 ? d_xh : d_gh;
    __half* Rout = STAGE1 ? d_r1 : d_r2;

    __shared__ float As[128 * R_];   // 8 KB: one 128-k chunk of A_e
    const int tid = threadIdx.x;
    const int row = tid >> 3;        // 0..31 (slot within m-block)
    const int ko  = tid & 7;         // k-eighth (16 k's per chunk)

    for (int mb = blockIdx.x; mb * 32 < ne; mb += 16) {
        const int slot = off + mb * 32 + row;      // may over-run this expert
        const __half* x = Xs + (size_t)slot * 1024;
        float acc[R_];
#pragma unroll
        for (int j = 0; j < R_; j++) acc[j] = 0.f;

        for (int k0 = 0; k0 < 1024; k0 += 128) {
            __syncthreads();   // protect As from previous chunk's readers
            {   // stage A chunk: 2048 floats, 8 per thread
                const float4* s = (const float4*)(Ae + k0 * R_) + tid * 2;
                float4 a = __ldg(s), b = __ldg(s + 1);
                ((float4*)As)[tid * 2]     = a;
                ((float4*)As)[tid * 2 + 1] = b;
            }
            __syncthreads();
            // this thread's 16 k's of the activation row
            const __half* xp = x + k0 + ko * 16;
            uint4 h0 = *(const uint4*)xp;
            uint4 h1 = *(const uint4*)(xp + 8);
            uint32_t hu[8] = {h0.x, h0.y, h0.z, h0.w, h1.x, h1.y, h1.z, h1.w};
            float xv[16];
#pragma unroll
            for (int q = 0; q < 8; q++) {
                float2 f = __half22float2(*(__half2*)&hu[q]);
                xv[2 * q] = f.x; xv[2 * q + 1] = f.y;
            }
#pragma unroll
            for (int kk = 0; kk < 16; kk++) {
                const float* ar = As + (ko * 16 + kk) * R_;
                float4 a0 = *(const float4*)ar;
                float4 a1 = *(const float4*)(ar + 4);
                float4 a2 = *(const float4*)(ar + 8);
                float4 a3 = *(const float4*)(ar + 12);
                float xvk = xv[kk];
                acc[0]  += xvk * a0.x; acc[1]  += xvk * a0.y;
                acc[2]  += xvk * a0.z; acc[3]  += xvk * a0.w;
                acc[4]  += xvk * a1.x; acc[5]  += xvk * a1.y;
                acc[6]  += xvk * a1.z; acc[7]  += xvk * a1.w;
                acc[8]  += xvk * a2.x; acc[9]  += xvk * a2.y;
                acc[10] += xvk * a2.z; acc[11] += xvk * a2.w;
                acc[12] += xvk * a3.x; acc[13] += xvk * a3.y;
                acc[14] += xvk * a3.z; acc[15] += xvk * a3.w;
            }
        }
        // reduce over the 8 lanes sharing this row (adjacent lanes in warp)
#pragma unroll
        for (int o = 4; o > 0; o >>= 1)
#pragma unroll
            for (int j = 0; j < R_; j++)
                acc[j] += __shfl_xor_sync(0xffffffffu, acc[j], o);
        // GUARD: only write slots belonging to THIS expert (over-run rows
        // are the next expert's slots — writing them corrupts its LoRA).
        if (ko == 0 && mb * 32 + row < ne) {
            uint32_t hw[8];
#pragma unroll
            for (int q = 0; q < 8; q++)
                asm("cvt.rn.f16x2.f32 %0, %1, %2;"
                    : "=r"(hw[q]) : "f"(acc[2 * q + 1]), "f"(acc[2 * q]));
            __half* rp = Rout + (size_t)slot * R_;
            *(uint4*)rp       = make_uint4(hw[0], hw[1], hw[2], hw[3]);
            *(uint4*)(rp + 8) = make_uint4(hw[4], hw[5], hw[6], hw[7]);
        }
        __syncthreads();   // As reuse safety across m-blocks
    }
}

// SMEM (static 20480 B), double-buffered f16, BK=16:
//   A[stage]: 128 rows x 48B (32B data + 16B pad)  @ s*6144
//   B[stage]: 16 k-rows x 256B (XOR-swizzled)      @ 12288 + s*4096
#define SM_A(s) ((s) * 6144)
#define SM_B(s) (12288 + (s) * 4096)

// ================= grouped GEMM: f16-act + fp32-W stream, 2-phase pipeline ==
// STAGE1: d_gh = act(xh @ Wgu + r1 @ LBgu + bias)   Ncols=2048
// STAGE2: out += w * (gh @ Wdn + r2 @ LBdn + bias)  Ncols=1024, atomics
// CTA 128x128, 8 warps (2m x 4n), warp 64x32, BK=16, 65 K-iters (incl LoRA).
template <bool STAGE1>
__global__ __launch_bounds__(256, 2)
void moe_mma_kernel(const float* __restrict__ W,     // [E,1024,Ncols] fp32
                    const float* __restrict__ LB,    // [E,16,Ncols] fp32
                    const float* __restrict__ bias,  // [E,Ncols] fp32
                    float* __restrict__ Out,         // final out (stage2)
                    int Ncols) {
    const int e  = blockIdx.z;
    const int ne = d_count[e];
    const int off = d_off[e];
    const int n0  = blockIdx.x * 128;
    const __half* Ah = STAGE1 ? d_xh : d_gh;
    const __half* Rh = STAGE1 ? d_r1 : d_r2;

    __shared__ __align__(16) char sm[20480];
    const uint32_t sb = smem_u32(sm);

    const int tid  = threadIdx.x;
    const int lane = tid & 31;
    const int wid  = tid >> 5;
    const int wm   = wid >> 2;       // 0..1 (64 rows)
    const int wn   = wid & 3;        // 0..3 (32 cols)

    // per-thread load mapping
    const int arow = tid >> 1;            // A: 2 threads/row, 16B f16 each
    const int akh  = (tid & 1) * 8;       // half-chunk in halves
    const int krow = tid >> 4;            // B: 0..15
    const int bc   = tid & 15;            // 8-float (32B) group -> 16B f16 chunk
    const uint32_t a_st = arow * 48 + (tid & 1) * 16;
    const uint32_t b_st = krow * 256 + ((bc ^ (krow & 7)) << 4);
    const float* bptr  = W  + ((size_t)e * 1024 + krow) * Ncols + n0 + bc * 8;
    const float* lbptr = LB + ((size_t)e * R_   + krow) * Ncols + n0 + bc * 8;

    for (int mb = blockIdx.y; mb * 128 < ne; mb += 4) {
        const int m0 = mb * 128;
        const int aslot = off + m0 + arow;        // pad rows: valid mem, junk ok
        const __half* asrc = Ah + (size_t)aslot * 1024 + akh;
        const __half* rsrc = Rh + (size_t)aslot * R_ + akh;

        float acc[4][4][4];
#pragma unroll
        for (int i = 0; i < 4; i++)
#pragma unroll
            for (int j = 0; j < 4; j++)
#pragma unroll
                for (int q = 0; q < 4; q++) acc[i][j][q] = 0.f;

        // named pipeline registers (no runtime-indexed arrays -> no lmem)
        uint4  paA, paB;
        float4 pb0A, pb1A, pb0B, pb1B;
        auto ldA = [&](int t, uint4& pa) {
            if (t > 64) return;
            const __half* p = (t < 64) ? (asrc + t * 16) : rsrc;
            pa = __ldg((const uint4*)p);
        };
        auto ldB = [&](int t, float4& b0, float4& b1) {
            if (t > 64) return;
            const float* p = (t < 64) ? (bptr + (size_t)t * 16 * Ncols) : lbptr;
            b0 = __ldg((const float4*)p);
            b1 = __ldg((const float4*)(p + 4));
        };
        auto stTile = [&](int s, const uint4 pa, const float4 b0, const float4 b1) {
            *(uint4*)(sm + SM_A(s) + a_st) = pa;
            *(uint4*)(sm + SM_B(s) + b_st) = cvt8_f16(b0, b1);
        };
        auto mmaTile = [&](int s) {
            const uint32_t sA = sb + SM_A(s);
            const uint32_t sB = sb + SM_B(s);
            uint32_t bh[2][4];
            {
                int k = ((lane >> 3) & 1) * 8 + (lane & 7);
                int cbase = (lane >> 4);
#pragma unroll
                for (int g = 0; g < 2; g++) {
                    int c = wn * 4 + g * 2 + cbase;
                    ldsm4t(bh[g], sB + k * 256 + ((c ^ (k & 7)) << 4));
                }
            }
#pragma unroll
            for (int mt = 0; mt < 4; mt++) {
                uint32_t ah[4];
                int m = wm * 64 + mt * 16 + (lane & 15);
                ldsm4(ah, sA + m * 48 + (lane >> 4) * 16);
#pragma unroll
                for (int nt = 0; nt < 4; nt++)
                    mma16816f(acc[mt][nt], ah, &bh[nt >> 1][(nt & 1) * 2]);
            }
        };

        // ---- prologue: tiles 0,1 in regs; tile 0 staged ----
        ldA(0, paA); ldB(0, pb0A, pb1A);
        ldA(1, paB); ldB(1, pb0B, pb1B);
        stTile(0, paA, pb0A, pb1A);
        __syncthreads();

        // ---- main loop: 2-phase, tile t issued ~2 bodies before its STS ----
        for (int it = 0; it < 64; it += 2) {
            // phase 0: consume smem[0] = tile it
            ldA(it + 2, paA); ldB(it + 2, pb0A, pb1A);
            mmaTile(0);
            stTile(1, paB, pb0B, pb1B);      // tile it+1
            __syncthreads();
            // phase 1: consume smem[1] = tile it+1
            ldA(it + 3, paB); ldB(it + 3, pb0B, pb1B);
            mmaTile(1);
            stTile(0, paA, pb0A, pb1A);      // tile it+2
            __syncthreads();
        }
        mmaTile(0);                           // tile 64 (LoRA)

        // ---- epilogue ----
        const float* be = bias + (size_t)e * Ncols + n0;
        float bb[4][2];
#pragma unroll
        for (int nt = 0; nt < 4; nt++) {
            int col = wn * 32 + nt * 8 + (lane & 3) * 2;
            bb[nt][0] = __ldg(be + col);
            bb[nt][1] = __ldg(be + col + 1);
        }
#pragma unroll
        for (int mt = 0; mt < 4; mt++) {
            int rbase = m0 + wm * 64 + mt * 16 + (lane >> 2);
#pragma unroll
            for (int half = 0; half < 2; half++) {
                int r = rbase + half * 8;
                if (r >= ne) continue;
                int slot = off + r;
                if (STAGE1) {
                    __half* orow = d_gh + (size_t)slot * 1024 + (n0 >> 1);
#pragma unroll
                    for (int nt = 0; nt < 4; nt++) {
                        float c0 = acc[mt][nt][half * 2]     + bb[nt][0];
                        float c1 = acc[mt][nt][half * 2 + 1] + bb[nt][1];
                        int col = wn * 32 + nt * 8 + (lane & 3) * 2;
                        float gate = fminf(c0, LIMIT_);
                        float up   = fminf(fmaxf(c1, -LIMIT_), LIMIT_);
                        float glu  = gate / (1.f + expf(-ACT_ALPHA_ * gate));
                        orow[col >> 1] = __float2half((up + 1.f) * glu);
                    }
                } else {
                    float wgt = d_slot_w[slot];
                    size_t orow = (size_t)d_slot_token[slot] * 1024 + n0;
#pragma unroll
                    for (int nt = 0; nt < 4; nt++) {
                        float c0 = acc[mt][nt][half * 2]     + bb[nt][0];
                        float c1 = acc[mt][nt][half * 2 + 1] + bb[nt][1];
                        int col = wn * 32 + nt * 8 + (lane & 3) * 2;
                        atomicAdd(Out + orow + col,     wgt * c0);
                        atomicAdd(Out + orow + col + 1, wgt * c1);
                    }
                }
            }
        }
        __syncthreads();  // smem safe for next m-block
    }
}

// ---------------- launch: kernel launches ONLY ------------------------------
extern "C" void kernel_launch(void* const* d_in, const int* in_sizes, int n_in,
                              void* d_out, int out_size) {
    const float* x     = (const float*)d_in[0];
    const int*   ridx  = (const int*)  d_in[1];
    const float* rw    = (const float*)d_in[2];
    const float* w_gu  = (const float*)d_in[3];
    const float* b_gu  = (const float*)d_in[4];
    const float* w_dn  = (const float*)d_in[5];
    const float* b_dn  = (const float*)d_in[6];
    const float* la_gu = (const float*)d_in[7];
    const float* lb_gu = (const float*)d_in[8];
    const float* la_dn = (const float*)d_in[9];
    const float* lb_dn = (const float*)d_in[10];
    float* out = (float*)d_out;

    route_kernel<<<1, 1024>>>(ridx, rw);
    zero_out_kernel<<<T_ * H_ / 1024, 256>>>(out);
    gather_xh_kernel<<<NSLOT, 256>>>(x);

    lora_r_kernel<true ><<<dim3(16, E_), 256>>>(la_gu);
    moe_mma_kernel<true ><<<dim3(D_ / 128, 4, E_), 256>>>(w_gu, lb_gu, b_gu,
                                                          nullptr, D_);
    lora_r_kernel<false><<<dim3(16, E_), 256>>>(la_dn);
    moe_mma_kernel<false><<<dim3(H_ / 128, 4, E_), 256>>>(w_dn, lb_dn, b_dn,
                                                          out, H_);
}

// round 17
// speedup vs baseline: 1.6836x; 1.6836x over previous
#include <cuda_runtime.h>
#include <cuda_bf16.h>
#include <cuda_fp16.h>
#include <math.h>
#include <stdint.h>

// Problem constants
#define E_    16
#define H_    1024
#define D_    2048
#define R_    16
#define T_    1024
#define NSLOT 2048
#define NPAD  (NSLOT + 128)
#define KSPLIT 8
#define LIMIT_   7.0f
#define ACT_ALPHA_ 1.702f

// ---------------- device scratch (~11.2 MB total) ---------------------------
__device__ int    d_count[E_];
__device__ int    d_off[E_];
__device__ int    d_slot_token[NSLOT];
__device__ int    d_slot_expert[NSLOT];
__device__ float  d_slot_w[NSLOT];
__device__ __half d_xh[(size_t)NPAD * 1024];   // gathered x, f16
__device__ __half d_gh[(size_t)NPAD * 1024];   // glu out, f16
__device__ __half d_r1[(size_t)NPAD * R_];     // lora acts f16
__device__ __half d_r2[(size_t)NPAD * R_];
__device__ float  d_rp[(size_t)KSPLIT * NSLOT * R_];  // k-split partials (2 MB)

// ---------------- helpers ----------------------------------------------------
__device__ __forceinline__ uint32_t smem_u32(const void* p) {
    return (uint32_t)__cvta_generic_to_shared(p);
}
__device__ __forceinline__ uint2 cvt4h(const float4 a) {
    uint2 r;
    asm("cvt.rn.f16x2.f32 %0, %1, %2;" : "=r"(r.x) : "f"(a.y), "f"(a.x));
    asm("cvt.rn.f16x2.f32 %0, %1, %2;" : "=r"(r.y) : "f"(a.w), "f"(a.z));
    return r;
}
__device__ __forceinline__ uint4 cvt8_f16(const float4 a, const float4 b) {
    uint4 r;
    asm("cvt.rn.f16x2.f32 %0, %1, %2;" : "=r"(r.x) : "f"(a.y), "f"(a.x));
    asm("cvt.rn.f16x2.f32 %0, %1, %2;" : "=r"(r.y) : "f"(a.w), "f"(a.z));
    asm("cvt.rn.f16x2.f32 %0, %1, %2;" : "=r"(r.z) : "f"(b.y), "f"(b.x));
    asm("cvt.rn.f16x2.f32 %0, %1, %2;" : "=r"(r.w) : "f"(b.w), "f"(b.z));
    return r;
}
__device__ __forceinline__ void ldsm4(uint32_t* r, uint32_t addr) {
    asm volatile("ldmatrix.sync.aligned.m8n8.x4.shared.b16 {%0,%1,%2,%3}, [%4];"
                 : "=r"(r[0]), "=r"(r[1]), "=r"(r[2]), "=r"(r[3]) : "r"(addr));
}
__device__ __forceinline__ void ldsm4t(uint32_t* r, uint32_t addr) {
    asm volatile("ldmatrix.sync.aligned.m8n8.x4.trans.shared.b16 {%0,%1,%2,%3}, [%4];"
                 : "=r"(r[0]), "=r"(r[1]), "=r"(r[2]), "=r"(r[3]) : "r"(addr));
}
__device__ __forceinline__ void mma16816f(float* d, const uint32_t* a,
                                          const uint32_t* b) {
    asm volatile(
        "mma.sync.aligned.m16n8k16.row.col.f32.f16.f16.f32 "
        "{%0,%1,%2,%3}, {%4,%5,%6,%7}, {%8,%9}, {%0,%1,%2,%3};"
        : "+f"(d[0]), "+f"(d[1]), "+f"(d[2]), "+f"(d[3])
        : "r"(a[0]), "r"(a[1]), "r"(a[2]), "r"(a[3]), "r"(b[0]), "r"(b[1]));
}

// ---------------- routing ---------------------------------------------------
__global__ void route_kernel(const int* __restrict__ ridx,
                             const float* __restrict__ rw) {
    __shared__ int cnt[E_], cur[E_], soff[E_ + 1];
    int t = threadIdx.x;
    if (t < E_) { cnt[t] = 0; cur[t] = 0; }
    __syncthreads();
    for (int i = t; i < NSLOT; i += blockDim.x)
        atomicAdd(&cnt[ridx[i]], 1);
    __syncthreads();
    if (t == 0) {
        int s = 0;
        for (int e = 0; e < E_; e++) { soff[e] = s; s += cnt[e]; }
        soff[E_] = s;
    }
    __syncthreads();
    for (int i = t; i < NSLOT; i += blockDim.x) {
        int e = ridx[i];
        int slot = soff[e] + atomicAdd(&cur[e], 1);
        d_slot_token[slot]  = i >> 1;
        d_slot_expert[slot] = e;
        d_slot_w[slot]      = rw[i];
    }
    if (t < E_) { d_count[t] = cnt[t]; d_off[t] = soff[t]; }
}

// ---------------- zero output ------------------------------------------------
__global__ void zero_out_kernel(float* __restrict__ out) {
    int i = blockIdx.x * 256 + threadIdx.x;
    *(float4*)&out[(size_t)i * 4] = make_float4(0.f, 0.f, 0.f, 0.f);
}

// ---------------- gather x rows -> f16 slot rows -----------------------------
__global__ void gather_xh_kernel(const float* __restrict__ x) {
    int slot = blockIdx.x;
    int tok  = d_slot_token[slot];
    int c    = threadIdx.x * 4;
    float4 v = __ldg((const float4*)&x[(size_t)tok * 1024 + c]);
    *(uint2*)&d_xh[(size_t)slot * 1024 + c] = cvt4h(v);
}

// ---------------- LoRA rank projection, k-split partials ---------------------
// Block (mb0, e, ks): 32 slots x 128-k chunk. A chunk staged ONCE per block.
// Writes fp32 partials d_rp[ks][slot][16]; finalize_r sums + converts.
template <bool STAGE1>
__global__ __launch_bounds__(256)
void lora_r_kernel(const float* __restrict__ A) {  // [E,1024,16] fp32
    const int e   = blockIdx.y;
    const int ks  = blockIdx.z;
    const int k0  = ks * 128;
    const int ne  = d_count[e];
    const int off = d_off[e];
    const float* Ae = A + (size_t)e * 1024 * R_;
    const __half* Xs = STAGE1 ? d_xh : d_gh;

    __shared__ float As[128 * R_];   // 8 KB: this block's 128-k chunk of A_e
    const int tid = threadIdx.x;
    const int row = tid >> 3;        // 0..31 (slot within m-block)
    const int ko  = tid & 7;         // k-sixteenth group (16 k's)

    {   // stage A chunk once: 2048 floats, 8 per thread
        const float4* s = (const float4*)(Ae + k0 * R_) + tid * 2;
        float4 a = __ldg(s), b = __ldg(s + 1);
        ((float4*)As)[tid * 2]     = a;
        ((float4*)As)[tid * 2 + 1] = b;
    }
    __syncthreads();

    for (int mb = blockIdx.x; mb * 32 < ne; mb += 4) {
        const int slot = off + mb * 32 + row;      // may over-run this expert
        float acc[R_];
#pragma unroll
        for (int j = 0; j < R_; j++) acc[j] = 0.f;

        const __half* xp = Xs + (size_t)slot * 1024 + k0 + ko * 16;
        uint4 h0 = *(const uint4*)xp;
        uint4 h1 = *(const uint4*)(xp + 8);
        uint32_t hu[8] = {h0.x, h0.y, h0.z, h0.w, h1.x, h1.y, h1.z, h1.w};
        float xv[16];
#pragma unroll
        for (int q = 0; q < 8; q++) {
            float2 f = __half22float2(*(__half2*)&hu[q]);
            xv[2 * q] = f.x; xv[2 * q + 1] = f.y;
        }
#pragma unroll
        for (int kk = 0; kk < 16; kk++) {
            const float* ar = As + (ko * 16 + kk) * R_;
            float4 a0 = *(const float4*)ar;
            float4 a1 = *(const float4*)(ar + 4);
            float4 a2 = *(const float4*)(ar + 8);
            float4 a3 = *(const float4*)(ar + 12);
            float xvk = xv[kk];
            acc[0]  += xvk * a0.x; acc[1]  += xvk * a0.y;
            acc[2]  += xvk * a0.z; acc[3]  += xvk * a0.w;
            acc[4]  += xvk * a1.x; acc[5]  += xvk * a1.y;
            acc[6]  += xvk * a1.z; acc[7]  += xvk * a1.w;
            acc[8]  += xvk * a2.x; acc[9]  += xvk * a2.y;
            acc[10] += xvk * a2.z; acc[11] += xvk * a2.w;
            acc[12] += xvk * a3.x; acc[13] += xvk * a3.y;
            acc[14] += xvk * a3.z; acc[15] += xvk * a3.w;
        }
        // reduce over the 8 adjacent lanes sharing this row
#pragma unroll
        for (int o = 4; o > 0; o >>= 1)
#pragma unroll
            for (int j = 0; j < R_; j++)
                acc[j] += __shfl_xor_sync(0xffffffffu, acc[j], o);
        // each of the 8 lanes writes its float2; guard against expert over-run
        if (mb * 32 + row < ne) {
            float* rp = d_rp + ((size_t)ks * NSLOT + slot) * R_ + 2 * ko;
            *(float2*)rp = make_float2(acc[2 * ko], acc[2 * ko + 1]);
        }
    }
}

// sum the KSPLIT partials and convert to f16
template <bool STAGE1>
__global__ void finalize_r_kernel() {
    int i = blockIdx.x * 256 + threadIdx.x;   // i < NSLOT*16
    int slot = i >> 4, j = i & 15;
    float s = 0.f;
#pragma unroll
    for (int ks = 0; ks < KSPLIT; ks++)
        s += d_rp[((size_t)ks * NSLOT + slot) * R_ + j];
    (STAGE1 ? d_r1 : d_r2)[(size_t)slot * R_ + j] = __float2half(s);
}

// SMEM (static 20480 B), double-buffered f16, BK=16:
//   A[stage]: 128 rows x 48B (32B data + 16B pad)  @ s*6144
//   B[stage]: 16 k-rows x 256B (XOR-swizzled)      @ 12288 + s*4096
#define SM_A(s) ((s) * 6144)
#define SM_B(s) (12288 + (s) * 4096)

// ================= grouped GEMM: f16-act + fp32-W stream, 2-phase pipeline ==
// STAGE1: d_gh = act(xh @ Wgu + r1 @ LBgu + bias)   Ncols=2048
// STAGE2: out += w * (gh @ Wdn + r2 @ LBdn + bias)  Ncols=1024, atomics
// CTA 128x128, 8 warps (2m x 4n), warp 64x32, BK=16, 65 K-iters (incl LoRA).
template <bool STAGE1>
__global__ __launch_bounds__(256, 2)
void moe_mma_kernel(const float* __restrict__ W,     // [E,1024,Ncols] fp32
                    const float* __restrict__ LB,    // [E,16,Ncols] fp32
                    const float* __restrict__ bias,  // [E,Ncols] fp32
                    float* __restrict__ Out,         // final out (stage2)
                    int Ncols) {
    const int e  = blockIdx.z;
    const int ne = d_count[e];
    const int off = d_off[e];
    const int n0  = blockIdx.x * 128;
    const __half* Ah = STAGE1 ? d_xh : d_gh;
    const __half* Rh = STAGE1 ? d_r1 : d_r2;

    __shared__ __align__(16) char sm[20480];
    const uint32_t sb = smem_u32(sm);

    const int tid  = threadIdx.x;
    const int lane = tid & 31;
    const int wid  = tid >> 5;
    const int wm   = wid >> 2;       // 0..1 (64 rows)
    const int wn   = wid & 3;        // 0..3 (32 cols)

    // per-thread load mapping
    const int arow = tid >> 1;            // A: 2 threads/row, 16B f16 each
    const int akh  = (tid & 1) * 8;       // half-chunk in halves
    const int krow = tid >> 4;            // B: 0..15
    const int bc   = tid & 15;            // 8-float (32B) group -> 16B f16 chunk
    const uint32_t a_st = arow * 48 + (tid & 1) * 16;
    const uint32_t b_st = krow * 256 + ((bc ^ (krow & 7)) << 4);
    const float* bptr  = W  + ((size_t)e * 1024 + krow) * Ncols + n0 + bc * 8;
    const float* lbptr = LB + ((size_t)e * R_   + krow) * Ncols + n0 + bc * 8;

    for (int mb = blockIdx.y; mb * 128 < ne; mb += 4) {
        const int m0 = mb * 128;
        const int aslot = off + m0 + arow;        // pad rows: valid mem, junk ok
        const __half* asrc = Ah + (size_t)aslot * 1024 + akh;
        const __half* rsrc = Rh + (size_t)aslot * R_ + akh;

        float acc[4][4][4];
#pragma unroll
        for (int i = 0; i < 4; i++)
#pragma unroll
            for (int j = 0; j < 4; j++)
#pragma unroll
                for (int q = 0; q < 4; q++) acc[i][j][q] = 0.f;

        // named pipeline registers (no runtime-indexed arrays -> no lmem)
        uint4  paA, paB;
        float4 pb0A, pb1A, pb0B, pb1B;
        auto ldA = [&](int t, uint4& pa) {
            if (t > 64) return;
            const __half* p = (t < 64) ? (asrc + t * 16) : rsrc;
            pa = __ldg((const uint4*)p);
        };
        auto ldB = [&](int t, float4& b0, float4& b1) {
            if (t > 64) return;
            const float* p = (t < 64) ? (bptr + (size_t)t * 16 * Ncols) : lbptr;
            b0 = __ldg((const float4*)p);
            b1 = __ldg((const float4*)(p + 4));
        };
        auto stTile = [&](int s, const uint4 pa, const float4 b0, const float4 b1) {
            *(uint4*)(sm + SM_A(s) + a_st) = pa;
            *(uint4*)(sm + SM_B(s) + b_st) = cvt8_f16(b0, b1);
        };
        auto mmaTile = [&](int s) {
            const uint32_t sA = sb + SM_A(s);
            const uint32_t sB = sb + SM_B(s);
            uint32_t bh[2][4];
            {
                int k = ((lane >> 3) & 1) * 8 + (lane & 7);
                int cbase = (lane >> 4);
#pragma unroll
                for (int g = 0; g < 2; g++) {
                    int c = wn * 4 + g * 2 + cbase;
                    ldsm4t(bh[g], sB + k * 256 + ((c ^ (k & 7)) << 4));
                }
            }
#pragma unroll
            for (int mt = 0; mt < 4; mt++) {
                uint32_t ah[4];
                int m = wm * 64 + mt * 16 + (lane & 15);
                ldsm4(ah, sA + m * 48 + (lane >> 4) * 16);
#pragma unroll
                for (int nt = 0; nt < 4; nt++)
                    mma16816f(acc[mt][nt], ah, &bh[nt >> 1][(nt & 1) * 2]);
            }
        };

        // ---- prologue: tiles 0,1 in regs; tile 0 staged ----
        ldA(0, paA); ldB(0, pb0A, pb1A);
        ldA(1, paB); ldB(1, pb0B, pb1B);
        stTile(0, paA, pb0A, pb1A);
        __syncthreads();

        // ---- main loop: 2-phase, tile t issued ~2 bodies before its STS ----
        for (int it = 0; it < 64; it += 2) {
            ldA(it + 2, paA); ldB(it + 2, pb0A, pb1A);
            mmaTile(0);
            stTile(1, paB, pb0B, pb1B);
            __syncthreads();
            ldA(it + 3, paB); ldB(it + 3, pb0B, pb1B);
            mmaTile(1);
            stTile(0, paA, pb0A, pb1A);
            __syncthreads();
        }
        mmaTile(0);                           // tile 64 (LoRA)

        // ---- epilogue ----
        const float* be = bias + (size_t)e * Ncols + n0;
        float bb[4][2];
#pragma unroll
        for (int nt = 0; nt < 4; nt++) {
            int col = wn * 32 + nt * 8 + (lane & 3) * 2;
            bb[nt][0] = __ldg(be + col);
            bb[nt][1] = __ldg(be + col + 1);
        }
#pragma unroll
        for (int mt = 0; mt < 4; mt++) {
            int rbase = m0 + wm * 64 + mt * 16 + (lane >> 2);
#pragma unroll
            for (int half = 0; half < 2; half++) {
                int r = rbase + half * 8;
                if (r >= ne) continue;
                int slot = off + r;
                if (STAGE1) {
                    __half* orow = d_gh + (size_t)slot * 1024 + (n0 >> 1);
#pragma unroll
                    for (int nt = 0; nt < 4; nt++) {
                        float c0 = acc[mt][nt][half * 2]     + bb[nt][0];
                        float c1 = acc[mt][nt][half * 2 + 1] + bb[nt][1];
                        int col = wn * 32 + nt * 8 + (lane & 3) * 2;
                        float gate = fminf(c0, LIMIT_);
                        float up   = fminf(fmaxf(c1, -LIMIT_), LIMIT_);
                        float glu  = gate / (1.f + expf(-ACT_ALPHA_ * gate));
                        orow[col >> 1] = __float2half((up + 1.f) * glu);
                    }
                } else {
                    float wgt = d_slot_w[slot];
                    size_t orow = (size_t)d_slot_token[slot] * 1024 + n0;
#pragma unroll
                    for (int nt = 0; nt < 4; nt++) {
                        float c0 = acc[mt][nt][half * 2]     + bb[nt][0];
                        float c1 = acc[mt][nt][half * 2 + 1] + bb[nt][1];
                        int col = wn * 32 + nt * 8 + (lane & 3) * 2;
                        atomicAdd(Out + orow + col,     wgt * c0);
                        atomicAdd(Out + orow + col + 1, wgt * c1);
                    }
                }
            }
        }
        __syncthreads();  // smem safe for next m-block
    }
}

// ---------------- launch: kernel launches ONLY ------------------------------
extern "C" void kernel_launch(void* const* d_in, const int* in_sizes, int n_in,
                              void* d_out, int out_size) {
    const float* x     = (const float*)d_in[0];
    const int*   ridx  = (const int*)  d_in[1];
    const float* rw    = (const float*)d_in[2];
    const float* w_gu  = (const float*)d_in[3];
    const float* b_gu  = (const float*)d_in[4];
    const float* w_dn  = (const float*)d_in[5];
    const float* b_dn  = (const float*)d_in[6];
    const float* la_gu = (const float*)d_in[7];
    const float* lb_gu = (const float*)d_in[8];
    const float* la_dn = (const float*)d_in[9];
    const float* lb_dn = (const float*)d_in[10];
    float* out = (float*)d_out;

    route_kernel<<<1, 1024>>>(ridx, rw);
    zero_out_kernel<<<T_ * H_ / 1024, 256>>>(out);
    gather_xh_kernel<<<NSLOT, 256>>>(x);

    lora_r_kernel<true ><<<dim3(4, E_, KSPLIT), 256>>>(la_gu);
    finalize_r_kernel<true ><<<NSLOT * R_ / 256, 256>>>();
    moe_mma_kernel<true ><<<dim3(D_ / 128, 4, E_), 256>>>(w_gu, lb_gu, b_gu,
                                                          nullptr, D_);
    lora_r_kernel<false><<<dim3(4, E_, KSPLIT), 256>>>(la_dn);
    finalize_r_kernel<false><<<NSLOT * R_ / 256, 256>>>();
    moe_mma_kernel<false><<<dim3(H_ / 128, 4, E_), 256>>>(w_dn, lb_dn, b_dn,
                                                          out, H_);
}